// round 1
// baseline (speedup 1.0000x reference)
#include <cuda_runtime.h>

#define IMG_H 480
#define IMG_W 640
#define IMG_HW (IMG_H * IMG_W)
#define OCH 64
#define KK 25            // 5x5
#define TKX 128          // tile width in pixels
#define TKY 8            // tile height in pixels
#define SW 132           // smem tile row width  (TKX + 4)
#define SH 12            // smem tile rows       (TKY + 4)
#define THREADS 256
#define THRESH 1e-4f

// ---- packed f32x2 helpers (Blackwell FFMA2 path, PTX-only) ----
__device__ __forceinline__ unsigned long long ffma2(unsigned long long a,
                                                    unsigned long long b,
                                                    unsigned long long c) {
    unsigned long long d;
    asm("fma.rn.f32x2 %0, %1, %2, %3;" : "=l"(d) : "l"(a), "l"(b), "l"(c));
    return d;
}
__device__ __forceinline__ unsigned long long pack2(float lo, float hi) {
    unsigned long long d;
    asm("mov.b64 %0, {%1, %2};" : "=l"(d) : "f"(lo), "f"(hi));
    return d;
}
__device__ __forceinline__ void unpack2(unsigned long long d, float& lo, float& hi) {
    asm("mov.b64 {%0, %1}, %2;" : "=f"(lo), "=f"(hi) : "l"(d));
}

__global__ __launch_bounds__(THREADS, 1)
void normdepthconv_kernel(const float* __restrict__ x,
                          const float* __restrict__ wt,
                          float* __restrict__ out) {
    __shared__ float tile[SH * SW];                 // 6336 B
    __shared__ unsigned long long w2s[OCH * KK];    // 12800 B, {w,w} pairs

    const int b  = blockIdx.z;
    const int X0 = blockIdx.x * TKX;
    const int Y0 = blockIdx.y * TKY;
    const int tid = threadIdx.x;

    // ---- cooperative halo-tile load (zero-padded borders) ----
    const float* xb = x + (size_t)b * IMG_HW;
    for (int i = tid; i < SH * SW; i += THREADS) {
        int r = i / SW;
        int c = i - r * SW;
        int gy = Y0 - 2 + r;
        int gx = X0 - 2 + c;
        float v = 0.f;
        if (gy >= 0 && gy < IMG_H && gx >= 0 && gx < IMG_W) v = xb[gy * IMG_W + gx];
        tile[i] = v;
    }
    // ---- weights, duplicated into both f32x2 halves ----
    for (int i = tid; i < OCH * KK; i += THREADS) {
        float w = wt[i];
        w2s[i] = pack2(w, w);
    }
    __syncthreads();

    const int tx = tid & 31;     // 32 threads across x, 4 pixels each -> 128
    const int ty = tid >> 5;     // 8 rows
    const int c0 = 4 * tx;       // smem col of leftmost needed value (x0-2)

    // ---- pass 1: box sums S and valid counts N for 4 pixels ----
    float S0 = 0.f, S1 = 0.f, S2 = 0.f, S3 = 0.f;
    float N0 = 0.f, N1 = 0.f, N2 = 0.f, N3 = 0.f;
#pragma unroll
    for (int dy = 0; dy < 5; ++dy) {
        const float4* row = reinterpret_cast<const float4*>(&tile[(ty + dy) * SW + c0]);
        float4 lo = row[0];
        float4 hi = row[1];
        float v[8] = {lo.x, lo.y, lo.z, lo.w, hi.x, hi.y, hi.z, hi.w};
        float m[8];
#pragma unroll
        for (int c = 0; c < 8; ++c) m[c] = (v[c] > THRESH) ? 1.f : 0.f;
#pragma unroll
        for (int kw = 0; kw < 5; ++kw) {
            S0 += v[kw];     N0 += m[kw];
            S1 += v[kw + 1]; N1 += m[kw + 1];
            S2 += v[kw + 2]; N2 += m[kw + 2];
            S3 += v[kw + 3]; N3 += m[kw + 3];
        }
    }
    const float ref0 = S0 / (N0 + 1e-6f);
    const float ref1 = S1 / (N1 + 1e-6f);
    const float ref2 = S2 / (N2 + 1e-6f);
    const float ref3 = S3 / (N3 + 1e-6f);

    // ---- pass 2: packed t-vectors  t[k] = mask * (ref - v) ----
    unsigned long long ta[KK];   // pixels 0,1
    unsigned long long tb[KK];   // pixels 2,3
#pragma unroll
    for (int dy = 0; dy < 5; ++dy) {
        const float4* row = reinterpret_cast<const float4*>(&tile[(ty + dy) * SW + c0]);
        float4 lo = row[0];
        float4 hi = row[1];
        float v[8] = {lo.x, lo.y, lo.z, lo.w, hi.x, hi.y, hi.z, hi.w};
#pragma unroll
        for (int kw = 0; kw < 5; ++kw) {
            const int k = dy * 5 + kw;
            float t0 = (v[kw]     > THRESH) ? (ref0 - v[kw])     : 0.f;
            float t1 = (v[kw + 1] > THRESH) ? (ref1 - v[kw + 1]) : 0.f;
            float t2 = (v[kw + 2] > THRESH) ? (ref2 - v[kw + 2]) : 0.f;
            float t3 = (v[kw + 3] > THRESH) ? (ref3 - v[kw + 3]) : 0.f;
            ta[k] = pack2(t0, t1);
            tb[k] = pack2(t2, t3);
        }
    }

    // ---- 64-channel packed GEMV + coalesced float4 stores ----
    float* outp = out + (size_t)b * OCH * IMG_HW + (size_t)(Y0 + ty) * IMG_W + (X0 + c0);
#pragma unroll 2
    for (int o = 0; o < OCH; ++o) {
        const unsigned long long* wrow = &w2s[o * KK];
        unsigned long long accA = 0ull;   // {0.f, 0.f}
        unsigned long long accB = 0ull;
#pragma unroll
        for (int k = 0; k < KK; ++k) {
            unsigned long long w = wrow[k];
            accA = ffma2(w, ta[k], accA);
            accB = ffma2(w, tb[k], accB);
        }
        float o0, o1, o2, o3;
        unpack2(accA, o0, o1);
        unpack2(accB, o2, o3);
        *reinterpret_cast<float4*>(outp + (size_t)o * IMG_HW) = make_float4(o0, o1, o2, o3);
    }
}

extern "C" void kernel_launch(void* const* d_in, const int* in_sizes, int n_in,
                              void* d_out, int out_size) {
    const float* x = (const float*)d_in[0];
    const float* w = (const float*)d_in[1];
    // defensive: metadata order should be (x, weight); swap if sizes say otherwise
    if (n_in >= 2 && in_sizes[0] == OCH * KK) {
        x = (const float*)d_in[1];
        w = (const float*)d_in[0];
    }
    dim3 grid(IMG_W / TKX, IMG_H / TKY, 8);   // 5 x 60 x 8 = 2400 CTAs
    normdepthconv_kernel<<<grid, THREADS>>>(x, w, (float*)d_out);
}

// round 2
// speedup vs baseline: 1.2425x; 1.2425x over previous
#include <cuda_runtime.h>

#define IMG_H 480
#define IMG_W 640
#define IMG_HW (IMG_H * IMG_W)
#define OCH 64
#define KK 25            // 5x5
#define KP 26            // padded row (u64 elems) so LDS.128 pairs stay aligned
#define TKX 128          // tile width in pixels
#define TKY 8            // tile height in pixels
#define SW 132           // smem tile row width  (TKX + 4)
#define SH 12            // smem tile rows       (TKY + 4)
#define THREADS 256
#define THRESH 1e-4f

// ---- packed f32x2 helpers (Blackwell FFMA2 path, PTX-only) ----
__device__ __forceinline__ unsigned long long ffma2(unsigned long long a,
                                                    unsigned long long b,
                                                    unsigned long long c) {
    unsigned long long d;
    asm("fma.rn.f32x2 %0, %1, %2, %3;" : "=l"(d) : "l"(a), "l"(b), "l"(c));
    return d;
}
__device__ __forceinline__ unsigned long long pack2(float lo, float hi) {
    unsigned long long d;
    asm("mov.b64 %0, {%1, %2};" : "=l"(d) : "f"(lo), "f"(hi));
    return d;
}
__device__ __forceinline__ void unpack2(unsigned long long d, float& lo, float& hi) {
    asm("mov.b64 {%0, %1}, %2;" : "=f"(lo), "=f"(hi) : "l"(d));
}

__global__ __launch_bounds__(THREADS, 2)
void normdepthconv_kernel(const float* __restrict__ x,
                          const float* __restrict__ wt,
                          float* __restrict__ out) {
    __shared__ float tile[SH * SW];                       // 6336 B
    __shared__ __align__(16) unsigned long long w2s[OCH * KP];  // 13312 B, {w,w} pairs

    const int b  = blockIdx.z;
    const int X0 = blockIdx.x * TKX;
    const int Y0 = blockIdx.y * TKY;
    const int tid = threadIdx.x;

    // ---- cooperative halo-tile load (zero-padded borders) ----
    const float* xb = x + (size_t)b * IMG_HW;
    for (int i = tid; i < SH * SW; i += THREADS) {
        int r = i / SW;
        int c = i - r * SW;
        int gy = Y0 - 2 + r;
        int gx = X0 - 2 + c;
        float v = 0.f;
        if (gy >= 0 && gy < IMG_H && gx >= 0 && gx < IMG_W) v = xb[gy * IMG_W + gx];
        tile[i] = v;
    }
    // ---- weights, duplicated into both f32x2 halves, rows padded to KP ----
    for (int i = tid; i < OCH * KK; i += THREADS) {
        int o = i / KK;
        int k = i - o * KK;
        float w = wt[i];
        w2s[o * KP + k] = pack2(w, w);
    }
    __syncthreads();

    const int tx = tid & 31;     // 32 threads across x, 4 pixels each -> 128
    const int ty = tid >> 5;     // 8 rows
    const int c0 = 4 * tx;       // smem col of leftmost needed value (x0-2)

    // ---- pass 1: box sums S and valid counts N for 4 pixels ----
    float S0 = 0.f, S1 = 0.f, S2 = 0.f, S3 = 0.f;
    float N0 = 0.f, N1 = 0.f, N2 = 0.f, N3 = 0.f;
#pragma unroll
    for (int dy = 0; dy < 5; ++dy) {
        const float4* row = reinterpret_cast<const float4*>(&tile[(ty + dy) * SW + c0]);
        float4 lo = row[0];
        float4 hi = row[1];
        float v[8] = {lo.x, lo.y, lo.z, lo.w, hi.x, hi.y, hi.z, hi.w};
        float m[8];
#pragma unroll
        for (int c = 0; c < 8; ++c) m[c] = (v[c] > THRESH) ? 1.f : 0.f;
#pragma unroll
        for (int kw = 0; kw < 5; ++kw) {
            S0 += v[kw];     N0 += m[kw];
            S1 += v[kw + 1]; N1 += m[kw + 1];
            S2 += v[kw + 2]; N2 += m[kw + 2];
            S3 += v[kw + 3]; N3 += m[kw + 3];
        }
    }
    const float ref0 = S0 / (N0 + 1e-6f);
    const float ref1 = S1 / (N1 + 1e-6f);
    const float ref2 = S2 / (N2 + 1e-6f);
    const float ref3 = S3 / (N3 + 1e-6f);

    // ---- pass 2: packed t-vectors  t[k] = mask * (ref - v) ----
    unsigned long long ta[KK];   // pixels 0,1
    unsigned long long tb[KK];   // pixels 2,3
#pragma unroll
    for (int dy = 0; dy < 5; ++dy) {
        const float4* row = reinterpret_cast<const float4*>(&tile[(ty + dy) * SW + c0]);
        float4 lo = row[0];
        float4 hi = row[1];
        float v[8] = {lo.x, lo.y, lo.z, lo.w, hi.x, hi.y, hi.z, hi.w};
#pragma unroll
        for (int kw = 0; kw < 5; ++kw) {
            const int k = dy * 5 + kw;
            float t0 = (v[kw]     > THRESH) ? (ref0 - v[kw])     : 0.f;
            float t1 = (v[kw + 1] > THRESH) ? (ref1 - v[kw + 1]) : 0.f;
            float t2 = (v[kw + 2] > THRESH) ? (ref2 - v[kw + 2]) : 0.f;
            float t3 = (v[kw + 3] > THRESH) ? (ref3 - v[kw + 3]) : 0.f;
            ta[k] = pack2(t0, t1);
            tb[k] = pack2(t2, t3);
        }
    }

    // ---- 64-channel packed GEMV: LDS.128 weight pairs + FFMA2 dual chains ----
    float* outp = out + (size_t)b * OCH * IMG_HW + (size_t)(Y0 + ty) * IMG_W + (X0 + c0);
#pragma unroll 2
    for (int o = 0; o < OCH; ++o) {
        const ulonglong2* wrow2 =
            reinterpret_cast<const ulonglong2*>(&w2s[o * KP]);
        unsigned long long accA = 0ull;   // {0.f, 0.f}
        unsigned long long accB = 0ull;
#pragma unroll
        for (int kp = 0; kp < 12; ++kp) {          // k = 2*kp, 2*kp+1
            ulonglong2 w = wrow2[kp];
            accA = ffma2(w.x, ta[2 * kp], accA);
            accB = ffma2(w.x, tb[2 * kp], accB);
            accA = ffma2(w.y, ta[2 * kp + 1], accA);
            accB = ffma2(w.y, tb[2 * kp + 1], accB);
        }
        {
            unsigned long long w24 = w2s[o * KP + 24];
            accA = ffma2(w24, ta[24], accA);
            accB = ffma2(w24, tb[24], accB);
        }
        float o0, o1, o2, o3;
        unpack2(accA, o0, o1);
        unpack2(accB, o2, o3);
        *reinterpret_cast<float4*>(outp + (size_t)o * IMG_HW) = make_float4(o0, o1, o2, o3);
    }
}

extern "C" void kernel_launch(void* const* d_in, const int* in_sizes, int n_in,
                              void* d_out, int out_size) {
    const float* x = (const float*)d_in[0];
    const float* w = (const float*)d_in[1];
    if (n_in >= 2 && in_sizes[0] == OCH * KK) {   // defensive input-order check
        x = (const float*)d_in[1];
        w = (const float*)d_in[0];
    }
    dim3 grid(IMG_W / TKX, IMG_H / TKY, 8);   // 5 x 60 x 8 = 2400 CTAs
    normdepthconv_kernel<<<grid, THREADS>>>(x, w, (float*)d_out);
}